// round 11
// baseline (speedup 1.0000x reference)
#include <cuda_runtime.h>
#include <cuda_bf16.h>

#define NN 50000
#define EE 1600000
#define ET (EE + NN)   // edges + self loops
#define IN_CH 128
#define H1C1 32        // 4 heads * 8
#define OUT_CH 64

// ---------------- scratch (device globals; no allocation allowed) ----------------
__device__ int   g_deg[NN];
__device__ int   g_off[NN + 1];
__device__ int   g_pos[NN];
__device__ int   g_csr[ET];              // src indices, grouped by dst
__device__ float g_h1[NN * H1C1];        // x @ W1            [N,4,8]
__device__ float g_asrc1[NN * 4];
__device__ float g_adst1[NN * 4];
__device__ float g_hr[NN * H1C1];        // relu(norm(agg1)+b1)
__device__ float g_h2[NN * OUT_CH];      // g_hr @ W2
__device__ float g_asrc2[NN];
__device__ float g_adst2[NN];

// ================= CSR construction (built once, used by both layers) =============
__global__ void zero_deg() {
    int i = blockIdx.x * blockDim.x + threadIdx.x;
    if (i < NN) g_deg[i] = 0;
}

__global__ void hist_kernel(const int* __restrict__ ei) {
    int e = blockIdx.x * blockDim.x + threadIdx.x;
    if (e >= ET) return;
    int dst = (e < EE) ? ei[EE + e] : e - EE;
    atomicAdd(&g_deg[dst], 1);
}

// single-block exclusive scan over 50K degrees
__global__ void scan_kernel() {
    __shared__ int sums[1024];
    const int CH = (NN + 1023) / 1024;   // 49
    int t = threadIdx.x;
    int beg = t * CH;
    int end = min(beg + CH, NN);
    int s = 0;
    for (int i = beg; i < end; i++) s += g_deg[i];
    sums[t] = s;
    __syncthreads();
    #pragma unroll
    for (int o = 1; o < 1024; o <<= 1) {
        int v = (t >= o) ? sums[t - o] : 0;
        __syncthreads();
        sums[t] += v;
        __syncthreads();
    }
    int run = (t == 0) ? 0 : sums[t - 1];
    for (int i = beg; i < end; i++) {
        g_off[i] = run;
        g_pos[i] = run;
        run += g_deg[i];
    }
    if (t == 1023) g_off[NN] = ET;
}

__global__ void fill_kernel(const int* __restrict__ ei) {
    int e = blockIdx.x * blockDim.x + threadIdx.x;
    if (e >= ET) return;
    int src, dst;
    if (e < EE) { src = ei[e]; dst = ei[EE + e]; }
    else        { src = dst = e - EE; }
    int idx = atomicAdd(&g_pos[dst], 1);
    g_csr[idx] = src;
}

// ---------------- layer 1 GEMM: h1 = x @ W1  (128 -> 32) ----------------
__global__ void gemm1_kernel(const float* __restrict__ x, const float* __restrict__ W1) {
    __shared__ float Ws[IN_CH * H1C1];   // 16 KB
    __shared__ float xs[8][IN_CH];
    int tid = threadIdx.x;
    for (int i = tid; i < IN_CH * H1C1; i += 256) Ws[i] = W1[i];
    int ty = tid >> 5, lane = tid & 31;
    int row = blockIdx.x * 8 + ty;
    if (row < NN) {
        #pragma unroll
        for (int k = lane; k < IN_CH; k += 32) xs[ty][k] = x[row * IN_CH + k];
    }
    __syncthreads();
    if (row < NN) {
        float acc = 0.f;
        #pragma unroll
        for (int k = 0; k < IN_CH; k++) acc += xs[ty][k] * Ws[k * H1C1 + lane];
        g_h1[row * H1C1 + lane] = acc;
    }
}

// ---------------- layer 1 attention coefficients ----------------
__global__ void att1_kernel(const float* __restrict__ att_src1, const float* __restrict__ att_dst1) {
    int i = blockIdx.x * blockDim.x + threadIdx.x;   // i = n*4 + h
    if (i >= NN * 4) return;
    int h = i & 3;
    const float* hp = g_h1 + (i >> 2) * H1C1 + h * 8;
    float s = 0.f, d = 0.f;
    #pragma unroll
    for (int c = 0; c < 8; c++) {
        float v = hp[c];
        s += v * att_src1[h * 8 + c];
        d += v * att_dst1[h * 8 + c];
    }
    g_asrc1[i] = s;
    g_adst1[i] = d;
}

// ---------------- layer 1 aggregation: warp per dst node, gather-only ------------
// out = relu( (sum_e w_e h1[src_e]) / (sum_e w_e + 1e-16) + b1 )
__global__ void agg1_kernel(const float* __restrict__ b1) {
    int n = (blockIdx.x * blockDim.x + threadIdx.x) >> 5;
    int lane = threadIdx.x & 31;
    if (n >= NN) return;
    int h = lane >> 3;
    float adst = __ldg(&g_adst1[n * 4 + h]);
    int beg = g_off[n], end = g_off[n + 1];
    float acc = 0.f, s = 0.f;
    int k = beg;
    for (; k + 3 < end; k += 4) {            // 4-way unroll for MLP
        int s0 = __ldg(&g_csr[k]);
        int s1 = __ldg(&g_csr[k + 1]);
        int s2 = __ldg(&g_csr[k + 2]);
        int s3 = __ldg(&g_csr[k + 3]);
        float l0 = __ldg(&g_asrc1[s0 * 4 + h]) + adst;
        float l1 = __ldg(&g_asrc1[s1 * 4 + h]) + adst;
        float l2 = __ldg(&g_asrc1[s2 * 4 + h]) + adst;
        float l3 = __ldg(&g_asrc1[s3 * 4 + h]) + adst;
        float v0 = __ldg(&g_h1[s0 * H1C1 + lane]);
        float v1 = __ldg(&g_h1[s1 * H1C1 + lane]);
        float v2 = __ldg(&g_h1[s2 * H1C1 + lane]);
        float v3 = __ldg(&g_h1[s3 * H1C1 + lane]);
        l0 = l0 > 0.f ? l0 : 0.2f * l0;
        l1 = l1 > 0.f ? l1 : 0.2f * l1;
        l2 = l2 > 0.f ? l2 : 0.2f * l2;
        l3 = l3 > 0.f ? l3 : 0.2f * l3;
        float w0 = __expf(l0);
        float w1 = __expf(l1);
        float w2 = __expf(l2);
        float w3 = __expf(l3);
        acc += w0 * v0 + w1 * v1 + w2 * v2 + w3 * v3;
        s += (w0 + w1) + (w2 + w3);
    }
    for (; k < end; k++) {
        int s0 = __ldg(&g_csr[k]);
        float l0 = __ldg(&g_asrc1[s0 * 4 + h]) + adst;
        l0 = l0 > 0.f ? l0 : 0.2f * l0;
        float w0 = __expf(l0);
        acc += w0 * __ldg(&g_h1[s0 * H1C1 + lane]);
        s += w0;
    }
    g_hr[n * H1C1 + lane] = fmaxf(acc / (s + 1e-16f) + b1[lane], 0.f);
}

// ---------------- layer 2 GEMM: h2 = g_hr @ W2  (32 -> 64) ----------------
__global__ void gemm2_kernel(const float* __restrict__ W2) {
    __shared__ float Ws[H1C1 * OUT_CH];  // 8 KB
    __shared__ float xs[4][H1C1];
    int tid = threadIdx.x;
    for (int i = tid; i < H1C1 * OUT_CH; i += 256) Ws[i] = W2[i];
    int ty = tid >> 6, col = tid & 63;
    int row = blockIdx.x * 4 + ty;
    if (row < NN && col < H1C1) xs[ty][col] = g_hr[row * H1C1 + col];
    __syncthreads();
    if (row < NN) {
        float acc = 0.f;
        #pragma unroll
        for (int k = 0; k < H1C1; k++) acc += xs[ty][k] * Ws[k * OUT_CH + col];
        g_h2[row * OUT_CH + col] = acc;
    }
}

// ---------------- layer 2 attention coefficients (warp per node) ----------------
__global__ void att2_kernel(const float* __restrict__ att_src2, const float* __restrict__ att_dst2) {
    int warp = (blockIdx.x * blockDim.x + threadIdx.x) >> 5;
    int lane = threadIdx.x & 31;
    if (warp >= NN) return;
    float s = 0.f, d = 0.f;
    #pragma unroll
    for (int c = lane; c < OUT_CH; c += 32) {
        float v = g_h2[warp * OUT_CH + c];
        s += v * att_src2[c];
        d += v * att_dst2[c];
    }
    #pragma unroll
    for (int o = 16; o; o >>= 1) {
        s += __shfl_down_sync(0xFFFFFFFFu, s, o);
        d += __shfl_down_sync(0xFFFFFFFFu, d, o);
    }
    if (lane == 0) { g_asrc2[warp] = s; g_adst2[warp] = d; }
}

// ---------------- layer 2 aggregation: warp per dst node, writes final out -------
__global__ void agg2_kernel(float* __restrict__ out, const float* __restrict__ b2) {
    int n = (blockIdx.x * blockDim.x + threadIdx.x) >> 5;
    int lane = threadIdx.x & 31;
    if (n >= NN) return;
    float adst = __ldg(&g_adst2[n]);
    int beg = g_off[n], end = g_off[n + 1];
    float acc0 = 0.f, acc1 = 0.f, s = 0.f;
    int k = beg;
    for (; k + 3 < end; k += 4) {            // 4-way unroll for MLP
        int s0 = __ldg(&g_csr[k]);
        int s1 = __ldg(&g_csr[k + 1]);
        int s2 = __ldg(&g_csr[k + 2]);
        int s3 = __ldg(&g_csr[k + 3]);
        float l0 = __ldg(&g_asrc2[s0]) + adst;
        float l1 = __ldg(&g_asrc2[s1]) + adst;
        float l2 = __ldg(&g_asrc2[s2]) + adst;
        float l3 = __ldg(&g_asrc2[s3]) + adst;
        float a0 = __ldg(&g_h2[s0 * OUT_CH + lane]);
        float a1 = __ldg(&g_h2[s0 * OUT_CH + lane + 32]);
        float b0 = __ldg(&g_h2[s1 * OUT_CH + lane]);
        float b1v = __ldg(&g_h2[s1 * OUT_CH + lane + 32]);
        float c0 = __ldg(&g_h2[s2 * OUT_CH + lane]);
        float c1 = __ldg(&g_h2[s2 * OUT_CH + lane + 32]);
        float d0 = __ldg(&g_h2[s3 * OUT_CH + lane]);
        float d1 = __ldg(&g_h2[s3 * OUT_CH + lane + 32]);
        l0 = l0 > 0.f ? l0 : 0.2f * l0;
        l1 = l1 > 0.f ? l1 : 0.2f * l1;
        l2 = l2 > 0.f ? l2 : 0.2f * l2;
        l3 = l3 > 0.f ? l3 : 0.2f * l3;
        float w0 = __expf(l0);
        float w1 = __expf(l1);
        float w2 = __expf(l2);
        float w3 = __expf(l3);
        acc0 += w0 * a0 + w1 * b0 + w2 * c0 + w3 * d0;
        acc1 += w0 * a1 + w1 * b1v + w2 * c1 + w3 * d1;
        s += (w0 + w1) + (w2 + w3);
    }
    for (; k < end; k++) {
        int s0 = __ldg(&g_csr[k]);
        float l0 = __ldg(&g_asrc2[s0]) + adst;
        l0 = l0 > 0.f ? l0 : 0.2f * l0;
        float w0 = __expf(l0);
        acc0 += w0 * __ldg(&g_h2[s0 * OUT_CH + lane]);
        acc1 += w0 * __ldg(&g_h2[s0 * OUT_CH + lane + 32]);
        s += w0;
    }
    float inv = 1.f / (s + 1e-16f);
    out[n * OUT_CH + lane]      = acc0 * inv + b2[lane];
    out[n * OUT_CH + lane + 32] = acc1 * inv + b2[lane + 32];
}

extern "C" void kernel_launch(void* const* d_in, const int* in_sizes, int n_in,
                              void* d_out, int out_size) {
    const float* x        = (const float*)d_in[0];
    const int*   ei       = (const int*)d_in[1];      // int32 (JAX x64 disabled)
    const float* W1       = (const float*)d_in[2];
    const float* att_src1 = (const float*)d_in[3];
    const float* att_dst1 = (const float*)d_in[4];
    const float* b1       = (const float*)d_in[5];
    const float* W2       = (const float*)d_in[6];
    const float* att_src2 = (const float*)d_in[7];
    const float* att_dst2 = (const float*)d_in[8];
    const float* b2       = (const float*)d_in[9];
    float* out = (float*)d_out;

    // ---- CSR build (once, reused by both layers) ----
    zero_deg<<<(NN + 255) / 256, 256>>>();
    hist_kernel<<<(ET + 255) / 256, 256>>>(ei);
    scan_kernel<<<1, 1024>>>();
    fill_kernel<<<(ET + 255) / 256, 256>>>(ei);

    // ---- layer 1 ----
    gemm1_kernel<<<(NN + 7) / 8, 256>>>(x, W1);
    att1_kernel<<<(NN * 4 + 255) / 256, 256>>>(att_src1, att_dst1);
    agg1_kernel<<<(NN * 32 + 255) / 256, 256>>>(b1);

    // ---- layer 2 ----
    gemm2_kernel<<<(NN + 3) / 4, 256>>>(W2);
    att2_kernel<<<(NN * 32 + 255) / 256, 256>>>(att_src2, att_dst2);
    agg2_kernel<<<(NN * 32 + 255) / 256, 256>>>(out, b2);
}

// round 12
// speedup vs baseline: 1.3506x; 1.3506x over previous
#include <cuda_runtime.h>
#include <cuda_bf16.h>

#define NN 50000
#define EE 1600000
#define ET (EE + NN)   // edges + self loops
#define IN_CH 128
#define H1C1 32        // 4 heads * 8
#define OUT_CH 64
#define NB 196         // ceil(NN/256) scan blocks

// ---------------- scratch (device globals; no allocation allowed) ----------------
__device__ int   g_deg[NN];
__device__ int   g_off[NN + 1];
__device__ int   g_pos[NN];
__device__ int   g_csr[ET];              // src indices, grouped by dst
__device__ int   g_bsum[NB];
__device__ int   g_boff[NB];
__device__ float g_h1[NN * H1C1];        // x @ W1            [N,4,8]
__device__ float g_asrc1[NN * 4];
__device__ float g_adst1[NN * 4];
__device__ float g_hr[NN * H1C1];        // relu(norm(agg1)+b1)
__device__ float g_h2[NN * OUT_CH];      // g_hr @ W2
__device__ float g_asrc2[NN];
__device__ float g_adst2[NN];

// ================= CSR construction (built once, used by both layers) =============
// deg starts at 1: every node has exactly one self loop.
__global__ void init_deg() {
    int i = blockIdx.x * blockDim.x + threadIdx.x;
    if (i < NN) g_deg[i] = 1;
}

// histogram real edges only; 4 per thread via int4 (dst half is contiguous, EE%4==0)
__global__ void hist_kernel(const int* __restrict__ ei) {
    int t = blockIdx.x * blockDim.x + threadIdx.x;
    int base = t * 4;
    if (base >= EE) return;
    int4 d = *reinterpret_cast<const int4*>(&ei[EE + base]);
    atomicAdd(&g_deg[d.x], 1);
    atomicAdd(&g_deg[d.y], 1);
    atomicAdd(&g_deg[d.z], 1);
    atomicAdd(&g_deg[d.w], 1);
}

// --- hierarchical exclusive scan over g_deg ---
__global__ void scan_partial() {                 // NB blocks x 256
    __shared__ int sh[256];
    int i = blockIdx.x * 256 + threadIdx.x;
    int v = (i < NN) ? g_deg[i] : 0;
    sh[threadIdx.x] = v;
    __syncthreads();
    // block reduce
    for (int o = 128; o; o >>= 1) {
        if (threadIdx.x < o) sh[threadIdx.x] += sh[threadIdx.x + o];
        __syncthreads();
    }
    if (threadIdx.x == 0) g_bsum[blockIdx.x] = sh[0];
}

__global__ void scan_tops() {                    // 1 block x 256
    __shared__ int sh[256];
    int t = threadIdx.x;
    sh[t] = (t < NB) ? g_bsum[t] : 0;
    __syncthreads();
    #pragma unroll
    for (int o = 1; o < 256; o <<= 1) {
        int v = (t >= o) ? sh[t - o] : 0;
        __syncthreads();
        sh[t] += v;
        __syncthreads();
    }
    if (t < NB) g_boff[t] = (t == 0) ? 0 : sh[t - 1];   // exclusive
}

// per-block exclusive scan + base offset; also plants self-loop at csr[off]
__global__ void scan_final() {                   // NB blocks x 256
    __shared__ int sh[256];
    int t = threadIdx.x;
    int i = blockIdx.x * 256 + t;
    int v = (i < NN) ? g_deg[i] : 0;
    sh[t] = v;
    __syncthreads();
    #pragma unroll
    for (int o = 1; o < 256; o <<= 1) {
        int u = (t >= o) ? sh[t - o] : 0;
        __syncthreads();
        sh[t] += u;
        __syncthreads();
    }
    if (i < NN) {
        int off = g_boff[blockIdx.x] + sh[t] - v;   // exclusive prefix
        g_off[i] = off;
        g_pos[i] = off + 1;       // slot 0 reserved for self loop
        g_csr[off] = i;           // self loop src
        if (i == NN - 1) g_off[NN] = ET;
    }
}

// scatter real edges; 2 per thread for ATOMG MLP (EE%2==0, int2-aligned halves)
__global__ void fill_kernel(const int* __restrict__ ei) {
    int t = blockIdx.x * blockDim.x + threadIdx.x;
    int base = t * 2;
    if (base >= EE) return;
    int2 s = *reinterpret_cast<const int2*>(&ei[base]);
    int2 d = *reinterpret_cast<const int2*>(&ei[EE + base]);
    int i0 = atomicAdd(&g_pos[d.x], 1);
    int i1 = atomicAdd(&g_pos[d.y], 1);
    g_csr[i0] = s.x;
    g_csr[i1] = s.y;
}

// ---------------- layer 1 GEMM: h1 = x @ W1  (128 -> 32) ----------------
__global__ void gemm1_kernel(const float* __restrict__ x, const float* __restrict__ W1) {
    __shared__ float Ws[IN_CH * H1C1];   // 16 KB
    __shared__ float xs[8][IN_CH];
    int tid = threadIdx.x;
    for (int i = tid; i < IN_CH * H1C1; i += 256) Ws[i] = W1[i];
    int ty = tid >> 5, lane = tid & 31;
    int row = blockIdx.x * 8 + ty;
    if (row < NN) {
        #pragma unroll
        for (int k = lane; k < IN_CH; k += 32) xs[ty][k] = x[row * IN_CH + k];
    }
    __syncthreads();
    if (row < NN) {
        float acc = 0.f;
        #pragma unroll
        for (int k = 0; k < IN_CH; k++) acc += xs[ty][k] * Ws[k * H1C1 + lane];
        g_h1[row * H1C1 + lane] = acc;
    }
}

// ---------------- layer 1 attention coefficients ----------------
__global__ void att1_kernel(const float* __restrict__ att_src1, const float* __restrict__ att_dst1) {
    int i = blockIdx.x * blockDim.x + threadIdx.x;   // i = n*4 + h
    if (i >= NN * 4) return;
    int h = i & 3;
    const float* hp = g_h1 + (i >> 2) * H1C1 + h * 8;
    float s = 0.f, d = 0.f;
    #pragma unroll
    for (int c = 0; c < 8; c++) {
        float v = hp[c];
        s += v * att_src1[h * 8 + c];
        d += v * att_dst1[h * 8 + c];
    }
    g_asrc1[i] = s;
    g_adst1[i] = d;
}

// ---------------- layer 1 aggregation: warp per dst node, gather-only ------------
__global__ void agg1_kernel(const float* __restrict__ b1) {
    int n = (blockIdx.x * blockDim.x + threadIdx.x) >> 5;
    int lane = threadIdx.x & 31;
    if (n >= NN) return;
    int h = lane >> 3;
    float adst = __ldg(&g_adst1[n * 4 + h]);
    int beg = g_off[n], end = g_off[n + 1];
    float acc = 0.f, s = 0.f;
    int k = beg;
    for (; k + 3 < end; k += 4) {            // 4-way unroll for MLP
        int s0 = __ldg(&g_csr[k]);
        int s1 = __ldg(&g_csr[k + 1]);
        int s2 = __ldg(&g_csr[k + 2]);
        int s3 = __ldg(&g_csr[k + 3]);
        float l0 = __ldg(&g_asrc1[s0 * 4 + h]) + adst;
        float l1 = __ldg(&g_asrc1[s1 * 4 + h]) + adst;
        float l2 = __ldg(&g_asrc1[s2 * 4 + h]) + adst;
        float l3 = __ldg(&g_asrc1[s3 * 4 + h]) + adst;
        float v0 = __ldg(&g_h1[s0 * H1C1 + lane]);
        float v1 = __ldg(&g_h1[s1 * H1C1 + lane]);
        float v2 = __ldg(&g_h1[s2 * H1C1 + lane]);
        float v3 = __ldg(&g_h1[s3 * H1C1 + lane]);
        l0 = l0 > 0.f ? l0 : 0.2f * l0;
        l1 = l1 > 0.f ? l1 : 0.2f * l1;
        l2 = l2 > 0.f ? l2 : 0.2f * l2;
        l3 = l3 > 0.f ? l3 : 0.2f * l3;
        float w0 = __expf(l0);
        float w1 = __expf(l1);
        float w2 = __expf(l2);
        float w3 = __expf(l3);
        acc += w0 * v0 + w1 * v1 + w2 * v2 + w3 * v3;
        s += (w0 + w1) + (w2 + w3);
    }
    for (; k < end; k++) {
        int s0 = __ldg(&g_csr[k]);
        float l0 = __ldg(&g_asrc1[s0 * 4 + h]) + adst;
        l0 = l0 > 0.f ? l0 : 0.2f * l0;
        float w0 = __expf(l0);
        acc += w0 * __ldg(&g_h1[s0 * H1C1 + lane]);
        s += w0;
    }
    g_hr[n * H1C1 + lane] = fmaxf(acc / (s + 1e-16f) + b1[lane], 0.f);
}

// ---------------- layer 2 GEMM: h2 = g_hr @ W2  (32 -> 64) ----------------
__global__ void gemm2_kernel(const float* __restrict__ W2) {
    __shared__ float Ws[H1C1 * OUT_CH];  // 8 KB
    __shared__ float xs[4][H1C1];
    int tid = threadIdx.x;
    for (int i = tid; i < H1C1 * OUT_CH; i += 256) Ws[i] = W2[i];
    int ty = tid >> 6, col = tid & 63;
    int row = blockIdx.x * 4 + ty;
    if (row < NN && col < H1C1) xs[ty][col] = g_hr[row * H1C1 + col];
    __syncthreads();
    if (row < NN) {
        float acc = 0.f;
        #pragma unroll
        for (int k = 0; k < H1C1; k++) acc += xs[ty][k] * Ws[k * OUT_CH + col];
        g_h2[row * OUT_CH + col] = acc;
    }
}

// ---------------- layer 2 attention coefficients (warp per node) ----------------
__global__ void att2_kernel(const float* __restrict__ att_src2, const float* __restrict__ att_dst2) {
    int warp = (blockIdx.x * blockDim.x + threadIdx.x) >> 5;
    int lane = threadIdx.x & 31;
    if (warp >= NN) return;
    float s = 0.f, d = 0.f;
    #pragma unroll
    for (int c = lane; c < OUT_CH; c += 32) {
        float v = g_h2[warp * OUT_CH + c];
        s += v * att_src2[c];
        d += v * att_dst2[c];
    }
    #pragma unroll
    for (int o = 16; o; o >>= 1) {
        s += __shfl_down_sync(0xFFFFFFFFu, s, o);
        d += __shfl_down_sync(0xFFFFFFFFu, d, o);
    }
    if (lane == 0) { g_asrc2[warp] = s; g_adst2[warp] = d; }
}

// ---------------- layer 2 aggregation: warp per dst, float2 per lane -------------
__global__ void agg2_kernel(float* __restrict__ out, const float* __restrict__ b2) {
    int n = (blockIdx.x * blockDim.x + threadIdx.x) >> 5;
    int lane = threadIdx.x & 31;
    if (n >= NN) return;
    const float2* h2v = reinterpret_cast<const float2*>(g_h2);   // [NN*32] float2
    float adst = __ldg(&g_adst2[n]);
    int beg = g_off[n], end = g_off[n + 1];
    float ax = 0.f, ay = 0.f, s = 0.f;
    int k = beg;
    for (; k + 3 < end; k += 4) {            // 4-way unroll for MLP
        int s0 = __ldg(&g_csr[k]);
        int s1 = __ldg(&g_csr[k + 1]);
        int s2 = __ldg(&g_csr[k + 2]);
        int s3 = __ldg(&g_csr[k + 3]);
        float l0 = __ldg(&g_asrc2[s0]) + adst;
        float l1 = __ldg(&g_asrc2[s1]) + adst;
        float l2 = __ldg(&g_asrc2[s2]) + adst;
        float l3 = __ldg(&g_asrc2[s3]) + adst;
        float2 v0 = __ldg(&h2v[s0 * 32 + lane]);
        float2 v1 = __ldg(&h2v[s1 * 32 + lane]);
        float2 v2 = __ldg(&h2v[s2 * 32 + lane]);
        float2 v3 = __ldg(&h2v[s3 * 32 + lane]);
        l0 = l0 > 0.f ? l0 : 0.2f * l0;
        l1 = l1 > 0.f ? l1 : 0.2f * l1;
        l2 = l2 > 0.f ? l2 : 0.2f * l2;
        l3 = l3 > 0.f ? l3 : 0.2f * l3;
        float w0 = __expf(l0);
        float w1 = __expf(l1);
        float w2 = __expf(l2);
        float w3 = __expf(l3);
        ax += w0 * v0.x + w1 * v1.x + w2 * v2.x + w3 * v3.x;
        ay += w0 * v0.y + w1 * v1.y + w2 * v2.y + w3 * v3.y;
        s += (w0 + w1) + (w2 + w3);
    }
    for (; k < end; k++) {
        int s0 = __ldg(&g_csr[k]);
        float l0 = __ldg(&g_asrc2[s0]) + adst;
        l0 = l0 > 0.f ? l0 : 0.2f * l0;
        float w0 = __expf(l0);
        float2 v0 = __ldg(&h2v[s0 * 32 + lane]);
        ax += w0 * v0.x;
        ay += w0 * v0.y;
        s += w0;
    }
    float inv = 1.f / (s + 1e-16f);
    float2 bb = __ldg(&reinterpret_cast<const float2*>(b2)[lane]);
    float2 r;
    r.x = ax * inv + bb.x;
    r.y = ay * inv + bb.y;
    reinterpret_cast<float2*>(out)[n * 32 + lane] = r;
}

extern "C" void kernel_launch(void* const* d_in, const int* in_sizes, int n_in,
                              void* d_out, int out_size) {
    const float* x        = (const float*)d_in[0];
    const int*   ei       = (const int*)d_in[1];      // int32 (JAX x64 disabled)
    const float* W1       = (const float*)d_in[2];
    const float* att_src1 = (const float*)d_in[3];
    const float* att_dst1 = (const float*)d_in[4];
    const float* b1       = (const float*)d_in[5];
    const float* W2       = (const float*)d_in[6];
    const float* att_src2 = (const float*)d_in[7];
    const float* att_dst2 = (const float*)d_in[8];
    const float* b2       = (const float*)d_in[9];
    float* out = (float*)d_out;

    // ---- CSR build (once, reused by both layers) ----
    init_deg<<<(NN + 255) / 256, 256>>>();
    hist_kernel<<<(EE / 4 + 255) / 256, 256>>>(ei);
    scan_partial<<<NB, 256>>>();
    scan_tops<<<1, 256>>>();
    scan_final<<<NB, 256>>>();
    fill_kernel<<<(EE / 2 + 255) / 256, 256>>>(ei);

    // ---- layer 1 ----
    gemm1_kernel<<<(NN + 7) / 8, 256>>>(x, W1);
    att1_kernel<<<(NN * 4 + 255) / 256, 256>>>(att_src1, att_dst1);
    agg1_kernel<<<(NN * 32 + 255) / 256, 256>>>(b1);

    // ---- layer 2 ----
    gemm2_kernel<<<(NN + 3) / 4, 256>>>(W2);
    att2_kernel<<<(NN * 32 + 255) / 256, 256>>>(att_src2, att_dst2);
    agg2_kernel<<<(NN * 32 + 255) / 256, 256>>>(out, b2);
}